// round 7
// baseline (speedup 1.0000x reference)
#include <cuda_runtime.h>

#define N 1024
#define T 512            // threads; each owns columns t and t+T
#define W (T / 32)       // 16 warps

// Order-preserving float -> uint32 mapping (exact, bijective, monotone).
__device__ __forceinline__ unsigned fkey(float f) {
    unsigned k = __float_as_uint(f);
    return (k & 0x80000000u) ? ~k : (k | 0x80000000u);
}
__device__ __forceinline__ float funkey(unsigned k) {
    unsigned b = (k & 0x80000000u) ? (k & 0x7fffffffu) : ~k;
    return __uint_as_float(b);
}
__device__ __forceinline__ float fdist(float4 row, float bx, float by, float bz) {
    const float dx = row.x - bx, dy = row.y - by, dz = row.z - bz;
    const float d2 = fmaf(dx, dx, fmaf(dy, dy, dz * dz));
    float c;
    asm("sqrt.approx.f32 %0, %1;" : "=f"(c) : "f"(d2));
    return c;
}
__device__ __forceinline__ unsigned long long umin64(unsigned long long a,
                                                     unsigned long long b) {
    return a < b ? a : b;
}

// Exact LAPJV: column-reduction warm start + shortest augmenting paths.
// 1 barrier per Dijkstra settle; cross-warp argmin via per-warp slots +
// register min-tree (no contended shared atomics). 512 threads x 2 columns.
__global__ __launch_bounds__(T, 1)
void emd_jv_kernel(const float* __restrict__ gt,
                   const float* __restrict__ gen,
                   float* __restrict__ out) {
    __shared__ float4 s_row[N];                 // {ax, ay, az, u}
    __shared__ int    s_p[N];                   // p[j] = row matched to col j (-1 free)
    __shared__ int    s_claim[N];               // CR row claims
    __shared__ unsigned short s_way[N];         // predecessor column on alt path
    __shared__ __align__(16) unsigned long long s_wb[2][W];  // per-warp candidates
    __shared__ float  s_sum[W];

    const int t    = threadIdx.x;
    const int lane = t & 31;
    const int wid  = t >> 5;
    const int jc0  = t, jc1 = t + T;

    // ---- init / load points ----
    float bx[2], by[2], bz[2];
    #pragma unroll
    for (int k = 0; k < 2; ++k) {
        const int r = t + k * T;
        s_row[r] = make_float4(gt[3 * r], gt[3 * r + 1], gt[3 * r + 2], 0.0f);
        s_p[r] = -1;
        s_claim[r] = 0x7fffffff;
        bx[k] = gen[3 * r]; by[k] = gen[3 * r + 1]; bz[k] = gen[3 * r + 2];
    }
    __syncthreads();

    // ---- phase 1: column reduction (v[j] = min_i C(i,j), claim argmin rows) ----
    float v[2] = {3.0e38f, 3.0e38f};
    int   bi[2] = {0, 0};
    for (int i = 0; i < N; ++i) {
        const float4 row = s_row[i];
        #pragma unroll
        for (int k = 0; k < 2; ++k) {
            const float c = fdist(row, bx[k], by[k], bz[k]);
            if (c < v[k]) { v[k] = c; bi[k] = i; }
        }
    }
    atomicMin(&s_claim[bi[0]], jc0);
    atomicMin(&s_claim[bi[1]], jc1);
    __syncthreads();
    if (s_claim[bi[0]] == jc0) s_p[jc0] = bi[0];
    if (s_claim[bi[1]] == jc1) s_p[jc1] = bi[1];
    __syncthreads();

    // ---- phase 2: shortest augmenting path for each free row ----
    for (int i = 0; i < N; ++i) {
        if (s_claim[i] != 0x7fffffff) continue; // pre-matched (uniform branch)
        __syncthreads();                        // prev augment + dual writes visible

        float M[2]  = {3.0e38f, 3.0e38f};
        bool  used[2] = {false, false};
        float Dj[2]; int pown[2];
        const int pj[2] = {s_p[jc0], s_p[jc1]}; // stable during the search
        float D  = 0.0f;
        int   i0 = i, j0 = N;
        int   j1f; float Dfinal;
        int   par = 0;

        while (true) {
            // ---- relax my free columns from (i0, D) ----
            const float4 row = s_row[i0];       // one LDS.128 broadcast
            #pragma unroll
            for (int k = 0; k < 2; ++k) {
                if (!used[k]) {
                    const float c = fdist(row, bx[k], by[k], bz[k]);
                    const float cand = (c - row.w - v[k]) + D;
                    if (cand < M[k]) {
                        M[k] = cand;
                        s_way[t + k * T] = (unsigned short)j0;
                    }
                }
            }
            const unsigned k0 = used[0] ? 0xffffffffu : fkey(M[0]);
            const unsigned k1 = used[1] ? 0xffffffffu : fkey(M[1]);
            unsigned key; unsigned long long pay;
            if (k0 <= k1) {                     // ties -> lower column index
                key = k0;
                pay = ((unsigned long long)k0 << 32) | ((unsigned)jc0 << 11)
                      | (unsigned)(pj[0] + 1);
            } else {
                key = k1;
                pay = ((unsigned long long)k1 << 32) | ((unsigned)jc1 << 11)
                      | (unsigned)(pj[1] + 1);
            }

            // ---- per-warp argmin -> private slot (no atomics) ----
            const unsigned wmin = __reduce_min_sync(0xffffffffu, key);
            const unsigned bal  = __ballot_sync(0xffffffffu, key == wmin);
            if (lane == (__ffs(bal) - 1)) s_wb[par][wid] = pay;
            __syncthreads();                    // the one barrier

            // ---- cross-warp min: broadcast LDS + register tree ----
            unsigned long long r[W / 2];
            const ulonglong2* wb = (const ulonglong2*)s_wb[par];
            #pragma unroll
            for (int q = 0; q < W / 2; ++q) {
                const ulonglong2 e = wb[q];
                r[q] = umin64(e.x, e.y);
            }
            #pragma unroll
            for (int s = W / 4; s; s >>= 1)
                #pragma unroll
                for (int q = 0; q < s; ++q) r[q] = umin64(r[q], r[q + s]);
            const unsigned long long best = r[0];
            par ^= 1;

            const float Dn  = funkey((unsigned)(best >> 32));
            const int   j1  = (int)((best >> 11) & 0x3ffu);
            const int   i0n = (int)(best & 0x7ffu) - 1;

            if (i0n >= 0) {
                if (j1 == jc0) { used[0] = true; Dj[0] = Dn; pown[0] = i0n; }
                if (j1 == jc1) { used[1] = true; Dj[1] = Dn; pown[1] = i0n; }
            } else {
                j1f = j1; Dfinal = Dn;
                break;
            }
            i0 = i0n; D = Dn; j0 = j1;
        }

        // ---- post-search dual updates (once per search) ----
        #pragma unroll
        for (int k = 0; k < 2; ++k)
            if (used[k]) {
                v[k] += Dj[k] - Dfinal;
                s_row[pown[k]].w += Dfinal - Dj[k];   // distinct rows: no conflict
            }
        if (t == 0) {
            s_row[i].w += Dfinal;               // u of newly assigned row
            int jj = j1f;                       // augment alternating path
            while (true) {
                const int jw = s_way[jj];
                if (jw == N) { s_p[jj] = i; break; }
                s_p[jj] = s_p[jw];
                jj = jw;
            }
        }
    }
    __syncthreads();

    // ---- mean of matched distances (exact sqrt) ----
    float acc = 0.0f;
    #pragma unroll
    for (int k = 0; k < 2; ++k) {
        const int jcol = t + k * T;
        const float4 row = s_row[s_p[jcol]];
        const float dx = row.x - bx[k], dy = row.y - by[k], dz = row.z - bz[k];
        acc += sqrtf(fmaf(dx, dx, fmaf(dy, dy, dz * dz)));
    }
    #pragma unroll
    for (int o = 16; o; o >>= 1) acc += __shfl_down_sync(0xffffffffu, acc, o);
    if (lane == 0) s_sum[wid] = acc;
    __syncthreads();
    if (t == 0) {
        float s = 0.0f;
        #pragma unroll
        for (int w = 0; w < W; ++w) s += s_sum[w];
        out[0] = s * (1.0f / (float)N);
    }
}

extern "C" void kernel_launch(void* const* d_in, const int* in_sizes, int n_in,
                              void* d_out, int out_size) {
    const float* gt  = (const float*)d_in[0];   // (1,1024,3) fp32
    const float* gen = (const float*)d_in[1];   // (1,1024,3) fp32
    (void)in_sizes; (void)n_in; (void)out_size;
    emd_jv_kernel<<<1, T>>>(gt, gen, (float*)d_out);
}

// round 8
// speedup vs baseline: 2.9879x; 2.9879x over previous
#include <cuda_runtime.h>

#define N   1024
#define T   1024
#define NW  32
#define RCAP 30000

// Order-preserving float -> uint32 mapping (exact, bijective, monotone).
__device__ __forceinline__ unsigned fkey(float f) {
    unsigned k = __float_as_uint(f);
    return (k & 0x80000000u) ? ~k : (k | 0x80000000u);
}
__device__ __forceinline__ float funkey(unsigned k) {
    unsigned b = (k & 0x80000000u) ? (k & 0x7fffffffu) : ~k;
    return __uint_as_float(b);
}
__device__ __forceinline__ float fdist4(float4 o, float bx, float by, float bz) {
    const float dx = o.x - bx, dy = o.y - by, dz = o.z - bz;
    const float d2 = fmaf(dx, dx, fmaf(dy, dy, dz * dz));
    float c; asm("sqrt.approx.f32 %0, %1;" : "=f"(c) : "f"(d2));
    return c;
}

// Jacobi auction with eps-scaling. Objects = gt rows (hold prices),
// bidders = gen points. Warp per bidder: top-2 min of (c+p) over all
// objects, bid via packed atomicMax (order-independent => deterministic).
__global__ __launch_bounds__(T, 1)
void emd_auction_kernel(const float* __restrict__ gt,
                        const float* __restrict__ gen,
                        float* __restrict__ out) {
    __shared__ float4 s_obj[N];                       // {x, y, z, price}
    __shared__ float  s_bx[N], s_by[N], s_bz[N];
    __shared__ unsigned long long s_slot[N];          // (fkey(pnew)<<32 | bidder)
    __shared__ short  s_owner[N];                     // object -> bidder (-1 free)
    __shared__ short  s_objof[N];                     // bidder -> object (-1 free)
    __shared__ unsigned short s_q[N];                 // unassigned bidders (sorted)
    __shared__ int    s_wcnt[NW], s_wpre[NW];
    __shared__ int    s_nq;
    __shared__ float  s_sum[NW];

    const int t = threadIdx.x, lane = t & 31, wid = t >> 5;

    s_obj[t] = make_float4(gt[3 * t], gt[3 * t + 1], gt[3 * t + 2], 0.0f);
    s_bx[t] = gen[3 * t]; s_by[t] = gen[3 * t + 1]; s_bz[t] = gen[3 * t + 2];
    s_slot[t] = 0ull;
    s_objof[t] = -1;

    float eps = 0.5f;
    int rounds = 0;                                   // uniform across threads

    for (int phase = 0; phase < 8; ++phase) {
        if (rounds < RCAP) {                          // uniform branch
            // reset assignment, keep prices
            s_owner[t] = -1; s_objof[t] = -1;
            s_q[t] = (unsigned short)t;
            if (t == 0) s_nq = N;
            __syncthreads();

            while (s_nq > 0 && rounds < RCAP) {
                ++rounds;
                const int nb = min(s_nq, NW);

                // ---- bidding: warp w = bidder s_q[w] ----
                if (wid < nb) {
                    const int j = s_q[wid];
                    const float bx = s_bx[j], by = s_by[j], bz = s_bz[j];
                    float m1 = 3.0e38f, m2 = 3.0e38f; int i1 = 0;
                    #pragma unroll 4
                    for (int k = 0; k < N / 32; ++k) {
                        const int i = lane + (k << 5);
                        const float4 o = s_obj[i];
                        const float c = fdist4(o, bx, by, bz) + o.w;
                        if (c < m1)      { m2 = m1; m1 = c; i1 = i; }
                        else if (c < m2) { m2 = c; }
                    }
                    #pragma unroll
                    for (int o = 16; o; o >>= 1) {      // warp top-2 reduce
                        const float om1 = __shfl_xor_sync(~0u, m1, o);
                        const float om2 = __shfl_xor_sync(~0u, m2, o);
                        const int   oi1 = __shfl_xor_sync(~0u, i1, o);
                        if (om1 < m1) { m2 = fminf(m1, om2); m1 = om1; i1 = oi1; }
                        else          { m2 = fminf(m2, om1); }
                    }
                    if (lane == 0) {
                        const float pnew = s_obj[i1].w + (m2 - m1) + eps;
                        atomicMax(&s_slot[i1],
                                  ((unsigned long long)fkey(pnew) << 32) | (unsigned)j);
                    }
                }
                __syncthreads();

                // ---- resolve: one object per thread ----
                {
                    const unsigned long long s = s_slot[t];
                    if (s) {
                        const int j = (int)(s & 0xffffffffu);
                        const int prev = s_owner[t];
                        if (prev >= 0) s_objof[prev] = -1;   // prev was assigned: != any winner
                        s_owner[t] = (short)j;
                        s_objof[j] = (short)t;
                        s_obj[t].w = funkey((unsigned)(s >> 32));
                        s_slot[t] = 0ull;
                    }
                }
                __syncthreads();

                // ---- rebuild unassigned queue (index order => deterministic) ----
                const bool un = (s_objof[t] < 0);
                const unsigned bal = __ballot_sync(~0u, un);
                if (lane == 0) s_wcnt[wid] = __popc(bal);
                __syncthreads();
                if (wid == 0) {
                    const int c = s_wcnt[lane];
                    int inc = c;
                    #pragma unroll
                    for (int o = 1; o < 32; o <<= 1) {
                        const int vv = __shfl_up_sync(~0u, inc, o);
                        if (lane >= o) inc += vv;
                    }
                    s_wpre[lane] = inc - c;
                    if (lane == 31) s_nq = inc;
                }
                __syncthreads();
                if (un)
                    s_q[s_wpre[wid] + __popc(bal & ((1u << lane) - 1u))] =
                        (unsigned short)t;
                __syncthreads();
            }
        }
        eps *= 0.25f;
    }

    // deterministic greedy completion (only if round cap hit; normally no-op)
    if (t == 0 && s_nq > 0) {
        for (int j = 0; j < N; ++j) if (s_objof[j] < 0) {
            for (int i = 0; i < N; ++i) if (s_owner[i] < 0) {
                s_owner[i] = (short)j; s_objof[j] = (short)i; break;
            }
        }
    }
    __syncthreads();

    // ---- exact mean of matched distances ----
    const int i = s_objof[t];
    const float4 o = s_obj[i];
    const float dx = o.x - s_bx[t], dy = o.y - s_by[t], dz = o.z - s_bz[t];
    float acc = sqrtf(fmaf(dx, dx, fmaf(dy, dy, dz * dz)));
    #pragma unroll
    for (int o2 = 16; o2; o2 >>= 1) acc += __shfl_down_sync(~0u, acc, o2);
    if (lane == 0) s_sum[wid] = acc;
    __syncthreads();
    if (t == 0) {
        float s = 0.0f;
        #pragma unroll
        for (int w = 0; w < NW; ++w) s += s_sum[w];
        out[0] = s * (1.0f / (float)N);
    }
}

extern "C" void kernel_launch(void* const* d_in, const int* in_sizes, int n_in,
                              void* d_out, int out_size) {
    const float* gt  = (const float*)d_in[0];   // (1,1024,3) fp32
    const float* gen = (const float*)d_in[1];   // (1,1024,3) fp32
    (void)in_sizes; (void)n_in; (void)out_size;
    emd_auction_kernel<<<1, T>>>(gt, gen, (float*)d_out);
}

// round 9
// speedup vs baseline: 3.3672x; 1.1269x over previous
#include <cuda_runtime.h>

#define N   1024
#define T   1024
#define NW  32
#define RCAP 30000

__device__ float g_dist[N * N];   // g_dist[j*N + i] = ||gen_j - gt_i|| (exact fp32)

// Order-preserving float -> uint32 mapping (exact, bijective, monotone).
__device__ __forceinline__ unsigned fkey(float f) {
    unsigned k = __float_as_uint(f);
    return (k & 0x80000000u) ? ~k : (k | 0x80000000u);
}
__device__ __forceinline__ float funkey(unsigned k) {
    unsigned b = (k & 0x80000000u) ? (k & 0x7fffffffu) : ~k;
    return __uint_as_float(b);
}

// ---- full-chip distance matrix precompute (amortized, exact sqrtf) ----
__global__ void dist_kernel(const float* __restrict__ gt,
                            const float* __restrict__ gen) {
    const int id = blockIdx.x * blockDim.x + threadIdx.x;   // 0 .. N*N-1
    const int j = id >> 10, i = id & (N - 1);
    const float dx = gen[3 * j]     - gt[3 * i];
    const float dy = gen[3 * j + 1] - gt[3 * i + 1];
    const float dz = gen[3 * j + 2] - gt[3 * i + 2];
    g_dist[id] = sqrtf(fmaf(dx, dx, fmaf(dy, dy, dz * dz)));
}

// Jacobi auction with eps-scaling over the precomputed matrix.
// Warp per bidder: top-2 min of (dist + price) over all objects,
// bid via packed atomicMax (order-independent => deterministic).
__global__ __launch_bounds__(T, 1)
void emd_auction_kernel(float* __restrict__ out) {
    __shared__ __align__(16) float s_price[N];
    __shared__ unsigned long long s_slot[N];          // (fkey(pnew)<<32 | bidder)
    __shared__ short  s_owner[N];                     // object -> bidder (-1 free)
    __shared__ short  s_objof[N];                     // bidder -> object (-1 free)
    __shared__ unsigned short s_q[N];                 // unassigned bidders (sorted)
    __shared__ int    s_wcnt[NW], s_wpre[NW];
    __shared__ int    s_nq;
    __shared__ float  s_sum[NW];

    const int t = threadIdx.x, lane = t & 31, wid = t >> 5;

    s_price[t] = 0.0f;
    s_slot[t]  = 0ull;
    s_objof[t] = -1;

    float eps = 0.5f;
    int rounds = 0;                                   // uniform across threads

    for (int phase = 0; phase < 8; ++phase) {
        if (rounds < RCAP) {                          // uniform branch
            // reset assignment, keep prices
            s_owner[t] = -1; s_objof[t] = -1;
            s_q[t] = (unsigned short)t;
            if (t == 0) s_nq = N;
            __syncthreads();

            while (s_nq > 0 && rounds < RCAP) {
                ++rounds;
                const int nb = min(s_nq, NW);

                // ---- bidding: warp w = bidder s_q[w] ----
                if (wid < nb) {
                    const int j = s_q[wid];
                    const float4* drow = (const float4*)(g_dist + j * N);
                    const float4* prow = (const float4*)s_price;
                    // two independent top-2 chains (halve serial compare depth)
                    float m1a = 3.0e38f, m2a = 3.0e38f; int i1a = 0;
                    float m1b = 3.0e38f, m2b = 3.0e38f; int i1b = 0;
                    #pragma unroll
                    for (int k = 0; k < 8; k += 2) {
                        {
                            const int q = k * 32 + lane;
                            const float4 d = drow[q], p = prow[q];
                            const int ib = q << 2;
                            float c;
                            c = d.x + p.x; if (c < m1a) { m2a = m1a; m1a = c; i1a = ib;     } else if (c < m2a) m2a = c;
                            c = d.y + p.y; if (c < m1a) { m2a = m1a; m1a = c; i1a = ib + 1; } else if (c < m2a) m2a = c;
                            c = d.z + p.z; if (c < m1a) { m2a = m1a; m1a = c; i1a = ib + 2; } else if (c < m2a) m2a = c;
                            c = d.w + p.w; if (c < m1a) { m2a = m1a; m1a = c; i1a = ib + 3; } else if (c < m2a) m2a = c;
                        }
                        {
                            const int q = (k + 1) * 32 + lane;
                            const float4 d = drow[q], p = prow[q];
                            const int ib = q << 2;
                            float c;
                            c = d.x + p.x; if (c < m1b) { m2b = m1b; m1b = c; i1b = ib;     } else if (c < m2b) m2b = c;
                            c = d.y + p.y; if (c < m1b) { m2b = m1b; m1b = c; i1b = ib + 1; } else if (c < m2b) m2b = c;
                            c = d.z + p.z; if (c < m1b) { m2b = m1b; m1b = c; i1b = ib + 2; } else if (c < m2b) m2b = c;
                            c = d.w + p.w; if (c < m1b) { m2b = m1b; m1b = c; i1b = ib + 3; } else if (c < m2b) m2b = c;
                        }
                    }
                    // merge the two chains
                    float m1, m2; int i1;
                    if (m1a <= m1b) { m1 = m1a; i1 = i1a; m2 = fminf(m2a, m1b); }
                    else            { m1 = m1b; i1 = i1b; m2 = fminf(m2b, m1a); }
                    #pragma unroll
                    for (int o = 16; o; o >>= 1) {      // warp top-2 reduce
                        const float om1 = __shfl_xor_sync(~0u, m1, o);
                        const float om2 = __shfl_xor_sync(~0u, m2, o);
                        const int   oi1 = __shfl_xor_sync(~0u, i1, o);
                        if (om1 < m1) { m2 = fminf(m1, om2); m1 = om1; i1 = oi1; }
                        else          { m2 = fminf(m2, om1); }
                    }
                    if (lane == 0) {
                        const float pnew = s_price[i1] + (m2 - m1) + eps;
                        atomicMax(&s_slot[i1],
                                  ((unsigned long long)fkey(pnew) << 32) | (unsigned)j);
                    }
                }
                __syncthreads();

                // ---- resolve: one object per thread ----
                {
                    const unsigned long long s = s_slot[t];
                    if (s) {
                        const int j = (int)(s & 0xffffffffu);
                        const int prev = s_owner[t];
                        if (prev >= 0) s_objof[prev] = -1;
                        s_owner[t] = (short)j;
                        s_objof[j] = (short)t;
                        s_price[t] = funkey((unsigned)(s >> 32));
                        s_slot[t] = 0ull;
                    }
                }
                __syncthreads();

                // ---- rebuild unassigned queue (index order => deterministic) ----
                const bool un = (s_objof[t] < 0);
                const unsigned bal = __ballot_sync(~0u, un);
                if (lane == 0) s_wcnt[wid] = __popc(bal);
                __syncthreads();
                if (wid == 0) {
                    const int c = s_wcnt[lane];
                    int inc = c;
                    #pragma unroll
                    for (int o = 1; o < 32; o <<= 1) {
                        const int vv = __shfl_up_sync(~0u, inc, o);
                        if (lane >= o) inc += vv;
                    }
                    s_wpre[lane] = inc - c;
                    if (lane == 31) s_nq = inc;
                }
                __syncthreads();
                if (un)
                    s_q[s_wpre[wid] + __popc(bal & ((1u << lane) - 1u))] =
                        (unsigned short)t;
                __syncthreads();
            }
        }
        eps *= 0.25f;
    }

    // deterministic greedy completion (only if round cap hit; normally no-op)
    if (t == 0 && s_nq > 0) {
        for (int j = 0; j < N; ++j) if (s_objof[j] < 0) {
            for (int i = 0; i < N; ++i) if (s_owner[i] < 0) {
                s_owner[i] = (short)j; s_objof[j] = (short)i; break;
            }
        }
    }
    __syncthreads();

    // ---- exact mean of matched distances (precomputed exact fp32) ----
    float acc = g_dist[t * N + (int)s_objof[t]];
    #pragma unroll
    for (int o2 = 16; o2; o2 >>= 1) acc += __shfl_down_sync(~0u, acc, o2);
    if (lane == 0) s_sum[wid] = acc;
    __syncthreads();
    if (t == 0) {
        float s = 0.0f;
        #pragma unroll
        for (int w = 0; w < NW; ++w) s += s_sum[w];
        out[0] = s * (1.0f / (float)N);
    }
}

extern "C" void kernel_launch(void* const* d_in, const int* in_sizes, int n_in,
                              void* d_out, int out_size) {
    const float* gt  = (const float*)d_in[0];   // (1,1024,3) fp32
    const float* gen = (const float*)d_in[1];   // (1,1024,3) fp32
    (void)in_sizes; (void)n_in; (void)out_size;
    dist_kernel<<<(N * N) / 256, 256>>>(gt, gen);
    emd_auction_kernel<<<1, T>>>((float*)d_out);
}